// round 12
// baseline (speedup 1.0000x reference)
#include <cuda_runtime.h>
#include <cuda_fp16.h>
#include <cstdint>

#define T_  4096
#define B_  8
#define D_  512
#define L_  128
#define H_  8
#define DH  64
#define LH  16
#define M_  (B_*T_)
#define NCH 64          // state-scan chunks
#define CSZ 64          // T_/NCH
#define NCA 128         // alpha chunks
#define CSA 32          // T_/NCA

// ---------------- scratch ----------------
__device__ float g_Q[M_*L_];
__device__ float g_K[M_*L_];
__device__ float g_V[M_*D_];
__device__ float g_csum[B_*NCA*L_];
__device__ float g_S[B_*H_*NCH*LH*DH];
__device__ unsigned short g_Xh[M_*D_];       // X fp16
__device__ unsigned short g_yh[M_*D_];       // scan out fp16 natural
__device__ unsigned short g_Yph[M_*D_];      // permuted fp16
__device__ unsigned short g_Wqkvh[(2*L_+D_)*D_];   // [768][512] fp16
__device__ unsigned short g_Woh[D_*D_];            // [512][512] fp16

// ---------------- PTX helpers ----------------
__device__ __forceinline__ uint32_t smem_u32(const void* p) {
    uint32_t a;
    asm("{ .reg .u64 t; cvta.to.shared.u64 t, %1; cvt.u32.u64 %0, t; }" : "=r"(a) : "l"(p));
    return a;
}
__device__ __forceinline__ void ldsm4(uint32_t* r, uint32_t addr) {
    asm volatile("ldmatrix.sync.aligned.m8n8.x4.shared.b16 {%0,%1,%2,%3}, [%4];"
                 : "=r"(r[0]), "=r"(r[1]), "=r"(r[2]), "=r"(r[3]) : "r"(addr));
}
__device__ __forceinline__ void mma16816(float* d, const uint32_t* a, const uint32_t* b) {
    asm volatile("mma.sync.aligned.m16n8k16.row.col.f32.f16.f16.f32 "
                 "{%0,%1,%2,%3}, {%4,%5,%6,%7}, {%8,%9}, {%0,%1,%2,%3};"
                 : "+f"(d[0]), "+f"(d[1]), "+f"(d[2]), "+f"(d[3])
                 : "r"(a[0]), "r"(a[1]), "r"(a[2]), "r"(a[3]), "r"(b[0]), "r"(b[1]));
}
#define CP_ASYNC16(dst, src) \
    asm volatile("cp.async.cg.shared.global [%0], [%1], 16;" :: "r"(dst), "l"(src))
#define CP_COMMIT() asm volatile("cp.async.commit_group;" ::: "memory")
#define CP_WAIT(n)  asm volatile("cp.async.wait_group %0;" :: "n"(n) : "memory")

// ============================================================
// fp16 1-term GEMM via mma.sync, fp32 acc. Tile 128x128, BK=32,
// 256 thr (2x4 warps, 64x32 warp tile), double-buffered cp.async.
// MODE 1: fused QKV epi (bx0 Q raw, bx1 K exp(0.125*), bx>=2 V)
// MODE 0: C[M,512] (O projection)
// ============================================================
#define ROWB 80
#define MATB (128 * ROWB)          // 10240
#define BUFB (2 * MATB)            // A,B
#define GEMM_SMEM (2 * BUFB)       // 40960

__device__ __forceinline__ void issue_loads(const unsigned short* ah,
                                            const unsigned short* bh,
                                            int k0, uint32_t smbuf, int tid)
{
#pragma unroll
    for (int half = 0; half < 2; half++) {
        int c = half * 256 + tid;
        int r = c >> 2, s = c & 3;
        uint32_t soff = (uint32_t)(r * ROWB + s * 16);
        CP_ASYNC16(smbuf + 0 * MATB + soff, ah + (size_t)r * 512 + k0 + s * 8);
        CP_ASYNC16(smbuf + 1 * MATB + soff, bh + (size_t)r * 512 + k0 + s * 8);
    }
}

template<int MODE>
__global__ __launch_bounds__(256, 2) void gemm_mma(const unsigned short* __restrict__ Ah,
                                                   const unsigned short* __restrict__ Bh,
                                                   float* __restrict__ C)
{
    extern __shared__ char sm[];
    const int tid = threadIdx.x;
    const int wid = tid >> 5, lane = tid & 31;
    const int wm = wid >> 2, wn = wid & 3;
    const int m0 = blockIdx.y * 128;
    const int n0 = blockIdx.x * 128;
    const uint32_t smb = smem_u32(sm);

    const unsigned short* ah = Ah + (size_t)m0 * 512;
    const unsigned short* bh = Bh + (size_t)n0 * 512;

    float acc[4][4][4];
#pragma unroll
    for (int i = 0; i < 4; i++)
#pragma unroll
        for (int j = 0; j < 4; j++)
#pragma unroll
            for (int e = 0; e < 4; e++) acc[i][j][e] = 0.f;

    const uint32_t a_lane = (uint32_t)((wm * 64 + (lane & 15)) * ROWB + (lane >> 4) * 16);
    const uint32_t b_lane = (uint32_t)((wn * 32 + (lane & 15)) * ROWB + (lane >> 4) * 16);

    issue_loads(ah, bh, 0, smb, tid);
    CP_COMMIT();

    const int NIT = 512 / 32;
    for (int ki = 0; ki < NIT; ki++) {
        const uint32_t buf = smb + (uint32_t)(ki & 1) * BUFB;
        if (ki + 1 < NIT) {
            issue_loads(ah, bh, (ki + 1) * 32, smb + (uint32_t)((ki + 1) & 1) * BUFB, tid);
            CP_COMMIT();
            CP_WAIT(1);
        } else {
            CP_WAIT(0);
        }
        __syncthreads();

#pragma unroll
        for (int ks = 0; ks < 2; ks++) {
            const uint32_t koff = (uint32_t)(ks * 32);
            uint32_t fBh[4][2];
#pragma unroll
            for (int p = 0; p < 2; p++) {
                uint32_t r[4];
                ldsm4(r, buf + 1 * MATB + b_lane + (uint32_t)(p * 16 * ROWB) + koff);
                fBh[2 * p][0] = r[0]; fBh[2 * p][1] = r[2];
                fBh[2 * p + 1][0] = r[1]; fBh[2 * p + 1][1] = r[3];
            }
#pragma unroll
            for (int mf = 0; mf < 4; mf++) {
                uint32_t fAh[4];
                ldsm4(fAh, buf + 0 * MATB + a_lane + (uint32_t)(mf * 16 * ROWB) + koff);
#pragma unroll
                for (int nf = 0; nf < 4; nf++)
                    mma16816(acc[mf][nf], fAh, fBh[nf]);
            }
        }
        __syncthreads();
    }

    // epilogue
    const int rr = lane >> 2, cc = (lane & 3) * 2;
    float* Cout;
    int cstride, colbase;
    bool do_exp = false;
    if (MODE == 1) {
        if (blockIdx.x == 0)      { Cout = g_Q; cstride = L_; colbase = 0; }
        else if (blockIdx.x == 1) { Cout = g_K; cstride = L_; colbase = 0; do_exp = true; }
        else                      { Cout = g_V; cstride = D_; colbase = (blockIdx.x - 2) * 128; }
    } else {
        Cout = C; cstride = D_; colbase = n0;
    }
#pragma unroll
    for (int mf = 0; mf < 4; mf++) {
#pragma unroll
        for (int nf = 0; nf < 4; nf++) {
            int row = m0 + wm * 64 + mf * 16 + rr;
            int col = colbase + wn * 32 + nf * 8 + cc;
            float d0 = acc[mf][nf][0], d1 = acc[mf][nf][1];
            float d2 = acc[mf][nf][2], d3 = acc[mf][nf][3];
            if (MODE == 1 && do_exp) {
                d0 = __expf(0.125f * d0); d1 = __expf(0.125f * d1);
                d2 = __expf(0.125f * d2); d3 = __expf(0.125f * d3);
            }
            *(float2*)(Cout + (size_t)row * cstride + col)       = make_float2(d0, d1);
            *(float2*)(Cout + (size_t)(row + 8) * cstride + col) = make_float2(d2, d3);
        }
    }
}

// ============================================================
// conversions (fp16 hi only)
// ============================================================
__global__ void conv_X(const float* __restrict__ X)
{
    int i = blockIdx.x * 256 + threadIdx.x;
    float4 v = ((const float4*)X)[i];
    ushort4 h;
    h.x = __half_as_ushort(__float2half(v.x));
    h.y = __half_as_ushort(__float2half(v.y));
    h.z = __half_as_ushort(__float2half(v.z));
    h.w = __half_as_ushort(__float2half(v.w));
    ((ushort4*)g_Xh)[i] = h;
}
// all four W[512][N] -> [N][512] fp16 transposes in one launch, tiled
__global__ __launch_bounds__(256) void conv_W_all(const float* __restrict__ Wq,
                                                  const float* __restrict__ Wk,
                                                  const float* __restrict__ Wv,
                                                  const float* __restrict__ Wo)
{
    __shared__ float ts[32][33];
    const int z = blockIdx.z;
    const float* W;
    unsigned short* Th;
    int N, roff;
    if (z == 0)      { W = Wq; Th = g_Wqkvh; N = L_; roff = 0; }
    else if (z == 1) { W = Wk; Th = g_Wqkvh; N = L_; roff = L_; }
    else if (z == 2) { W = Wv; Th = g_Wqkvh; N = D_; roff = 2 * L_; }
    else             { W = Wo; Th = g_Woh;   N = D_; roff = 0; }
    const int n0 = blockIdx.x * 32, k0 = blockIdx.y * 32;
    if (n0 >= N) return;
    const int tid = threadIdx.x;
#pragma unroll
    for (int i = 0; i < 4; i++) {
        int f = i * 256 + tid;
        int kk = f >> 5, nn = f & 31;
        ts[kk][nn] = W[(size_t)(k0 + kk) * N + n0 + nn];
    }
    __syncthreads();
#pragma unroll
    for (int i = 0; i < 4; i++) {
        int f = i * 256 + tid;
        int nn = f >> 5, kk = f & 31;
        Th[(size_t)(roff + n0 + nn) * 512 + k0 + kk] =
            __half_as_ushort(__float2half(ts[kk][nn]));
    }
}

// ============================================================
// alpha cumsum (NCA=128 chunks); p3 fuses softmax + normalize
// ============================================================
__global__ void alpha_p1()
{
    int chunk = blockIdx.x, b = blockIdx.y, l = threadIdx.x;
    float s = 0.f;
    int base = (b * T_ + chunk * CSA) * L_ + l;
    for (int i = 0; i < CSA; i++) s += g_K[base + i * L_];
    g_csum[(b * NCA + chunk) * L_ + l] = s;
}
__global__ void alpha_p2()
{
    int b = blockIdx.x, l = threadIdx.x;
    float run = 0.f;
    for (int c = 0; c < NCA; c++) {
        int idx = (b * NCA + c) * L_ + l;
        float v = g_csum[idx];
        g_csum[idx] = run;
        run += v;
    }
}
__global__ void alpha_p3()
{
    int chunk = blockIdx.x, b = blockIdx.y, l = threadIdx.x;
    float a = g_csum[(b * NCA + chunk) * L_ + l];
    int base = (b * T_ + chunk * CSA) * L_ + l;
    for (int i = 0; i < CSA; i++) {
        int idx = base + i * L_;
        a += g_K[idx];
        float q = g_Q[idx] * 0.125f;
        float m = q;
#pragma unroll
        for (int s = 8; s >= 1; s >>= 1)
            m = fmaxf(m, __shfl_xor_sync(0xffffffffu, m, s));
        float e = __expf(q - m);
        float sum = e;
#pragma unroll
        for (int s = 8; s >= 1; s >>= 1)
            sum += __shfl_xor_sync(0xffffffffu, sum, s);
        g_Q[idx] = __fdividef(e, sum * a);
    }
}

// ============================================================
// state scan (NCH=64 chunks of 64)
// ============================================================
__global__ __launch_bounds__(128) void state_p1()
{
    int chunk = blockIdx.x, h = blockIdx.y, b = blockIdx.z;
    int tid = threadIdx.x;
    int l = tid >> 3, d0 = (tid & 7) * 8;
    __shared__ float ke_s[16][16];
    __shared__ float v_s[16][64];
    float acc[8] = {0, 0, 0, 0, 0, 0, 0, 0};
    int t0 = chunk * CSZ;
    for (int tt = 0; tt < CSZ; tt += 16) {
#pragma unroll
        for (int r = 0; r < 2; r++) {
            int f = r * 128 + tid, tr = f >> 4, li = f & 15;
            ke_s[tr][li] = g_K[(b * T_ + t0 + tt + tr) * L_ + h * LH + li];
        }
#pragma unroll
        for (int r = 0; r < 2; r++) {
            int f = r * 128 + tid, tr = f >> 4, dq = f & 15;
            *(float4*)&v_s[tr][dq * 4] =
                *(const float4*)&g_V[(b * T_ + t0 + tt + tr) * D_ + h * DH + dq * 4];
        }
        __syncthreads();
#pragma unroll
        for (int k = 0; k < 16; k++) {
            float kl = ke_s[k][l];
            float4 va = *(const float4*)&v_s[k][d0];
            float4 vb = *(const float4*)&v_s[k][d0 + 4];
            acc[0] = fmaf(kl, va.x, acc[0]); acc[1] = fmaf(kl, va.y, acc[1]);
            acc[2] = fmaf(kl, va.z, acc[2]); acc[3] = fmaf(kl, va.w, acc[3]);
            acc[4] = fmaf(kl, vb.x, acc[4]); acc[5] = fmaf(kl, vb.y, acc[5]);
            acc[6] = fmaf(kl, vb.z, acc[6]); acc[7] = fmaf(kl, vb.w, acc[7]);
        }
        __syncthreads();
    }
    float* Sp = &g_S[(((b * H_ + h) * NCH + chunk) * LH + l) * DH + d0];
    *(float4*)Sp       = make_float4(acc[0], acc[1], acc[2], acc[3]);
    *(float4*)(Sp + 4) = make_float4(acc[4], acc[5], acc[6], acc[7]);
}
__global__ void state_p2()
{
    int bh = blockIdx.x, tid = threadIdx.x;
    float4 run = make_float4(0, 0, 0, 0);
    for (int c = 0; c < NCH; c++) {
        float4* p = (float4*)&g_S[(size_t)(bh * NCH + c) * (LH * DH) + tid * 4];
        float4 v = *p;
        *p = run;
        run.x += v.x; run.y += v.y; run.z += v.z; run.w += v.w;
    }
}
__global__ __launch_bounds__(64) void scan_p3()
{
    int chunk = blockIdx.x, h = blockIdx.y, b = blockIdx.z;
    int tid = threadIdx.x;
    __shared__ float ke_s[16][16];
    __shared__ float w_s[16][16];
    __shared__ float v_s[16][64];
    float carry[16];
    const float* Sp = &g_S[(size_t)((b * H_ + h) * NCH + chunk) * (LH * DH)];
#pragma unroll
    for (int l = 0; l < 16; l++) carry[l] = Sp[l * 64 + tid];
    int t0 = chunk * CSZ;

    for (int tt = 0; tt < CSZ; tt += 16) {
#pragma unroll
        for (int r = 0; r < 4; r++) {
            int f = r * 64 + tid, tr = f >> 4, li = f & 15;
            int src = (b * T_ + t0 + tt + tr) * L_ + h * LH + li;
            ke_s[tr][li] = g_K[src];
            w_s[tr][li]  = g_Q[src];
        }
#pragma unroll
        for (int r = 0; r < 4; r++) {
            int f = r * 64 + tid, tr = f >> 4, dq = f & 15;
            *(float4*)&v_s[tr][dq * 4] =
                *(const float4*)&g_V[(b * T_ + t0 + tt + tr) * D_ + h * DH + dq * 4];
        }
        __syncthreads();
#pragma unroll
        for (int k = 0; k < 16; k++) {
            float v = v_s[k][tid];
            float4 ke0 = *(const float4*)&ke_s[k][0];
            float4 ke1 = *(const float4*)&ke_s[k][4];
            float4 ke2 = *(const float4*)&ke_s[k][8];
            float4 ke3 = *(const float4*)&ke_s[k][12];
            float4 w0 = *(const float4*)&w_s[k][0];
            float4 w1 = *(const float4*)&w_s[k][4];
            float4 w2 = *(const float4*)&w_s[k][8];
            float4 w3 = *(const float4*)&w_s[k][12];
            float y = 0.f;
            carry[0]  = fmaf(ke0.x, v, carry[0]);  y = fmaf(w0.x, carry[0],  y);
            carry[1]  = fmaf(ke0.y, v, carry[1]);  y = fmaf(w0.y, carry[1],  y);
            carry[2]  = fmaf(ke0.z, v, carry[2]);  y = fmaf(w0.z, carry[2],  y);
            carry[3]  = fmaf(ke0.w, v, carry[3]);  y = fmaf(w0.w, carry[3],  y);
            carry[4]  = fmaf(ke1.x, v, carry[4]);  y = fmaf(w1.x, carry[4],  y);
            carry[5]  = fmaf(ke1.y, v, carry[5]);  y = fmaf(w1.y, carry[5],  y);
            carry[6]  = fmaf(ke1.z, v, carry[6]);  y = fmaf(w1.z, carry[6],  y);
            carry[7]  = fmaf(ke1.w, v, carry[7]);  y = fmaf(w1.w, carry[7],  y);
            carry[8]  = fmaf(ke2.x, v, carry[8]);  y = fmaf(w2.x, carry[8],  y);
            carry[9]  = fmaf(ke2.y, v, carry[9]);  y = fmaf(w2.y, carry[9],  y);
            carry[10] = fmaf(ke2.z, v, carry[10]); y = fmaf(w2.z, carry[10], y);
            carry[11] = fmaf(ke2.w, v, carry[11]); y = fmaf(w2.w, carry[11], y);
            carry[12] = fmaf(ke3.x, v, carry[12]); y = fmaf(w3.x, carry[12], y);
            carry[13] = fmaf(ke3.y, v, carry[13]); y = fmaf(w3.y, carry[13], y);
            carry[14] = fmaf(ke3.z, v, carry[14]); y = fmaf(w3.z, carry[14], y);
            carry[15] = fmaf(ke3.w, v, carry[15]); y = fmaf(w3.w, carry[15], y);
            g_yh[(b * T_ + t0 + tt + k) * D_ + h * DH + tid] =
                __half_as_ushort(__float2half(y));
        }
        __syncthreads();
    }
}

// ============================================================
// permutation (fp16 shuffle)
// ============================================================
__global__ __launch_bounds__(256) void transpose_k()
{
    int t8 = blockIdx.x, b = blockIdx.y;
    int tid = threadIdx.x;
    __shared__ unsigned short ys[8][512];
#pragma unroll
    for (int r = 0; r < 2; r++) {
        int f = r * 256 + tid, tr = f >> 6, c8 = f & 63;
        *(uint4*)&ys[tr][c8 * 8] =
            *(const uint4*)&g_yh[(size_t)(b * T_ + t8 * 8 + tr) * D_ + c8 * 8];
    }
    __syncthreads();
#pragma unroll
    for (int r = 0; r < 2; r++) {
        int p = r * 256 + tid;
        int k = p >> 6, dh = p & 63;
        unsigned short v[8];
#pragma unroll
        for (int hh = 0; hh < 8; hh++) v[hh] = ys[k][hh * 64 + dh];
        int bp = dh >> 3, e = dh & 7;
        size_t didx = (size_t)bp * (T_ * D_) + (size_t)(e * 512 + t8) * D_ + k * 64 + b * 8;
        *(uint4*)(g_Yph + didx) = *(uint4*)v;
    }
}

// ============================================================
extern "C" void kernel_launch(void* const* d_in, const int* in_sizes, int n_in,
                              void* d_out, int out_size)
{
    const float* X  = (const float*)d_in[0];
    const float* Wk = (const float*)d_in[1];
    const float* Wq = (const float*)d_in[2];
    const float* Wv = (const float*)d_in[3];
    const float* Wo = (const float*)d_in[4];
    float* out = (float*)d_out;

    unsigned short *pXh, *pYph, *pWqkvh, *pWoh;
    cudaGetSymbolAddress((void**)&pXh, g_Xh);
    cudaGetSymbolAddress((void**)&pYph, g_Yph);
    cudaGetSymbolAddress((void**)&pWqkvh, g_Wqkvh);
    cudaGetSymbolAddress((void**)&pWoh, g_Woh);

    cudaFuncSetAttribute(gemm_mma<0>, cudaFuncAttributeMaxDynamicSharedMemorySize, GEMM_SMEM);
    cudaFuncSetAttribute(gemm_mma<1>, cudaFuncAttributeMaxDynamicSharedMemorySize, GEMM_SMEM);

    // conversions
    conv_X<<<M_ * D_ / 1024, 256>>>(X);
    conv_W_all<<<dim3(16, 16, 4), 256>>>(Wq, Wk, Wv, Wo);

    // fused QKV projection (1-term fp16)
    gemm_mma<1><<<dim3(6, 256), 256, GEMM_SMEM>>>(pXh, pWqkvh, nullptr);

    // alpha cumsum + fused softmax/normalize
    alpha_p1<<<dim3(NCA, B_), 128>>>();
    alpha_p2<<<B_, 128>>>();
    alpha_p3<<<dim3(NCA, B_), 128>>>();

    // chunk-parallel state scan
    state_p1<<<dim3(NCH, H_, B_), 128>>>();
    state_p2<<<B_ * H_, 256>>>();
    scan_p3<<<dim3(NCH, H_, B_), 64>>>();

    // permutation + O projection (1-term fp16)
    transpose_k<<<dim3(T_ / 8, B_), 256>>>();
    gemm_mma<0><<<dim3(4, 256), 256, GEMM_SMEM>>>(pYph, pWoh, out);
}

// round 13
// speedup vs baseline: 1.0046x; 1.0046x over previous
#include <cuda_runtime.h>
#include <cuda_fp16.h>
#include <cstdint>

#define T_  4096
#define B_  8
#define D_  512
#define L_  128
#define H_  8
#define DH  64
#define LH  16
#define M_  (B_*T_)
#define NCH 64          // state-scan chunks
#define CSZ 64          // T_/NCH
#define NCA 128         // alpha chunks
#define CSA 32          // T_/NCA

// ---------------- scratch ----------------
__device__ float g_Q[M_*L_];
__device__ float g_K[M_*L_];
__device__ float g_V[M_*D_];
__device__ float g_csum[B_*NCA*L_];
__device__ float g_S[B_*H_*NCH*LH*DH];
__device__ unsigned short g_Xh[M_*D_];       // X fp16
__device__ unsigned short g_yh[M_*D_];       // scan out fp16 natural
__device__ unsigned short g_Yph[M_*D_];      // permuted fp16
__device__ unsigned short g_Wqkvh[(2*L_+D_)*D_];   // [768][512] fp16
__device__ unsigned short g_Woh[D_*D_];            // [512][512] fp16

// ---------------- PTX helpers ----------------
__device__ __forceinline__ uint32_t smem_u32(const void* p) {
    uint32_t a;
    asm("{ .reg .u64 t; cvta.to.shared.u64 t, %1; cvt.u32.u64 %0, t; }" : "=r"(a) : "l"(p));
    return a;
}
__device__ __forceinline__ void ldsm4(uint32_t* r, uint32_t addr) {
    asm volatile("ldmatrix.sync.aligned.m8n8.x4.shared.b16 {%0,%1,%2,%3}, [%4];"
                 : "=r"(r[0]), "=r"(r[1]), "=r"(r[2]), "=r"(r[3]) : "r"(addr));
}
__device__ __forceinline__ void mma16816(float* d, const uint32_t* a, const uint32_t* b) {
    asm volatile("mma.sync.aligned.m16n8k16.row.col.f32.f16.f16.f32 "
                 "{%0,%1,%2,%3}, {%4,%5,%6,%7}, {%8,%9}, {%0,%1,%2,%3};"
                 : "+f"(d[0]), "+f"(d[1]), "+f"(d[2]), "+f"(d[3])
                 : "r"(a[0]), "r"(a[1]), "r"(a[2]), "r"(a[3]), "r"(b[0]), "r"(b[1]));
}
#define CP_ASYNC16(dst, src) \
    asm volatile("cp.async.cg.shared.global [%0], [%1], 16;" :: "r"(dst), "l"(src))
#define CP_COMMIT() asm volatile("cp.async.commit_group;" ::: "memory")
#define CP_WAIT(n)  asm volatile("cp.async.wait_group %0;" :: "n"(n) : "memory")

// ============================================================
// fp16 1-term GEMM via mma.sync, fp32 acc. Tile 128x128, BK=32,
// 256 thr (2x4 warps, 64x32 warp tile), double-buffered cp.async.
// MODE 1: fused QKV epi (bx0 Q raw, bx1 K exp(0.125*), bx>=2 V)
// MODE 0: C[M,512] (O projection)
// ============================================================
#define ROWB 80
#define MATB (128 * ROWB)          // 10240
#define BUFB (2 * MATB)            // A,B
#define GEMM_SMEM (2 * BUFB)       // 40960

__device__ __forceinline__ void issue_loads(const unsigned short* ah,
                                            const unsigned short* bh,
                                            int k0, uint32_t smbuf, int tid)
{
#pragma unroll
    for (int half = 0; half < 2; half++) {
        int c = half * 256 + tid;
        int r = c >> 2, s = c & 3;
        uint32_t soff = (uint32_t)(r * ROWB + s * 16);
        CP_ASYNC16(smbuf + 0 * MATB + soff, ah + (size_t)r * 512 + k0 + s * 8);
        CP_ASYNC16(smbuf + 1 * MATB + soff, bh + (size_t)r * 512 + k0 + s * 8);
    }
}

template<int MODE>
__global__ __launch_bounds__(256, 2) void gemm_mma(const unsigned short* __restrict__ Ah,
                                                   const unsigned short* __restrict__ Bh,
                                                   float* __restrict__ C)
{
    extern __shared__ char sm[];
    const int tid = threadIdx.x;
    const int wid = tid >> 5, lane = tid & 31;
    const int wm = wid >> 2, wn = wid & 3;
    const int m0 = blockIdx.y * 128;
    const int n0 = blockIdx.x * 128;
    const uint32_t smb = smem_u32(sm);

    const unsigned short* ah = Ah + (size_t)m0 * 512;
    const unsigned short* bh = Bh + (size_t)n0 * 512;

    float acc[4][4][4];
#pragma unroll
    for (int i = 0; i < 4; i++)
#pragma unroll
        for (int j = 0; j < 4; j++)
#pragma unroll
            for (int e = 0; e < 4; e++) acc[i][j][e] = 0.f;

    const uint32_t a_lane = (uint32_t)((wm * 64 + (lane & 15)) * ROWB + (lane >> 4) * 16);
    const uint32_t b_lane = (uint32_t)((wn * 32 + (lane & 15)) * ROWB + (lane >> 4) * 16);

    issue_loads(ah, bh, 0, smb, tid);
    CP_COMMIT();

    const int NIT = 512 / 32;
    for (int ki = 0; ki < NIT; ki++) {
        const uint32_t buf = smb + (uint32_t)(ki & 1) * BUFB;
        if (ki + 1 < NIT) {
            issue_loads(ah, bh, (ki + 1) * 32, smb + (uint32_t)((ki + 1) & 1) * BUFB, tid);
            CP_COMMIT();
            CP_WAIT(1);
        } else {
            CP_WAIT(0);
        }
        __syncthreads();

#pragma unroll
        for (int ks = 0; ks < 2; ks++) {
            const uint32_t koff = (uint32_t)(ks * 32);
            uint32_t fBh[4][2];
#pragma unroll
            for (int p = 0; p < 2; p++) {
                uint32_t r[4];
                ldsm4(r, buf + 1 * MATB + b_lane + (uint32_t)(p * 16 * ROWB) + koff);
                fBh[2 * p][0] = r[0]; fBh[2 * p][1] = r[2];
                fBh[2 * p + 1][0] = r[1]; fBh[2 * p + 1][1] = r[3];
            }
#pragma unroll
            for (int mf = 0; mf < 4; mf++) {
                uint32_t fAh[4];
                ldsm4(fAh, buf + 0 * MATB + a_lane + (uint32_t)(mf * 16 * ROWB) + koff);
#pragma unroll
                for (int nf = 0; nf < 4; nf++)
                    mma16816(acc[mf][nf], fAh, fBh[nf]);
            }
        }
        __syncthreads();
    }

    // epilogue
    const int rr = lane >> 2, cc = (lane & 3) * 2;
    float* Cout;
    int cstride, colbase;
    bool do_exp = false;
    if (MODE == 1) {
        if (blockIdx.x == 0)      { Cout = g_Q; cstride = L_; colbase = 0; }
        else if (blockIdx.x == 1) { Cout = g_K; cstride = L_; colbase = 0; do_exp = true; }
        else                      { Cout = g_V; cstride = D_; colbase = (blockIdx.x - 2) * 128; }
    } else {
        Cout = C; cstride = D_; colbase = n0;
    }
#pragma unroll
    for (int mf = 0; mf < 4; mf++) {
#pragma unroll
        for (int nf = 0; nf < 4; nf++) {
            int row = m0 + wm * 64 + mf * 16 + rr;
            int col = colbase + wn * 32 + nf * 8 + cc;
            float d0 = acc[mf][nf][0], d1 = acc[mf][nf][1];
            float d2 = acc[mf][nf][2], d3 = acc[mf][nf][3];
            if (MODE == 1 && do_exp) {
                d0 = __expf(0.125f * d0); d1 = __expf(0.125f * d1);
                d2 = __expf(0.125f * d2); d3 = __expf(0.125f * d3);
            }
            *(float2*)(Cout + (size_t)row * cstride + col)       = make_float2(d0, d1);
            *(float2*)(Cout + (size_t)(row + 8) * cstride + col) = make_float2(d2, d3);
        }
    }
}

// ============================================================
// conversions (fp16 hi only)
// ============================================================
__global__ void conv_X(const float* __restrict__ X)
{
    int i = blockIdx.x * 256 + threadIdx.x;
    float4 v = ((const float4*)X)[i];
    ushort4 h;
    h.x = __half_as_ushort(__float2half(v.x));
    h.y = __half_as_ushort(__float2half(v.y));
    h.z = __half_as_ushort(__float2half(v.z));
    h.w = __half_as_ushort(__float2half(v.w));
    ((ushort4*)g_Xh)[i] = h;
}
// all four W[512][N] -> [N][512] fp16 transposes in one launch, tiled
__global__ __launch_bounds__(256) void conv_W_all(const float* __restrict__ Wq,
                                                  const float* __restrict__ Wk,
                                                  const float* __restrict__ Wv,
                                                  const float* __restrict__ Wo)
{
    __shared__ float ts[32][33];
    const int z = blockIdx.z;
    const float* W;
    unsigned short* Th;
    int N, roff;
    if (z == 0)      { W = Wq; Th = g_Wqkvh; N = L_; roff = 0; }
    else if (z == 1) { W = Wk; Th = g_Wqkvh; N = L_; roff = L_; }
    else if (z == 2) { W = Wv; Th = g_Wqkvh; N = D_; roff = 2 * L_; }
    else             { W = Wo; Th = g_Woh;   N = D_; roff = 0; }
    const int n0 = blockIdx.x * 32, k0 = blockIdx.y * 32;
    if (n0 >= N) return;
    const int tid = threadIdx.x;
#pragma unroll
    for (int i = 0; i < 4; i++) {
        int f = i * 256 + tid;
        int kk = f >> 5, nn = f & 31;
        ts[kk][nn] = W[(size_t)(k0 + kk) * N + n0 + nn];
    }
    __syncthreads();
#pragma unroll
    for (int i = 0; i < 4; i++) {
        int f = i * 256 + tid;
        int nn = f >> 5, kk = f & 31;
        Th[(size_t)(roff + n0 + nn) * 512 + k0 + kk] =
            __half_as_ushort(__float2half(ts[kk][nn]));
    }
}

// ============================================================
// alpha cumsum (NCA=128 chunks); p3 fuses softmax + normalize
// ============================================================
__global__ void alpha_p1()
{
    int chunk = blockIdx.x, b = blockIdx.y, l = threadIdx.x;
    float s = 0.f;
    int base = (b * T_ + chunk * CSA) * L_ + l;
    for (int i = 0; i < CSA; i++) s += g_K[base + i * L_];
    g_csum[(b * NCA + chunk) * L_ + l] = s;
}
__global__ void alpha_p2()
{
    int b = blockIdx.x, l = threadIdx.x;
    float run = 0.f;
    for (int c = 0; c < NCA; c++) {
        int idx = (b * NCA + c) * L_ + l;
        float v = g_csum[idx];
        g_csum[idx] = run;
        run += v;
    }
}
__global__ void alpha_p3()
{
    int chunk = blockIdx.x, b = blockIdx.y, l = threadIdx.x;
    float a = g_csum[(b * NCA + chunk) * L_ + l];
    int base = (b * T_ + chunk * CSA) * L_ + l;
    for (int i = 0; i < CSA; i++) {
        int idx = base + i * L_;
        a += g_K[idx];
        float q = g_Q[idx] * 0.125f;
        float m = q;
#pragma unroll
        for (int s = 8; s >= 1; s >>= 1)
            m = fmaxf(m, __shfl_xor_sync(0xffffffffu, m, s));
        float e = __expf(q - m);
        float sum = e;
#pragma unroll
        for (int s = 8; s >= 1; s >>= 1)
            sum += __shfl_xor_sync(0xffffffffu, sum, s);
        g_Q[idx] = __fdividef(e, sum * a);
    }
}

// ============================================================
// state scan (NCH=64 chunks of 64)
// ============================================================
__global__ __launch_bounds__(128) void state_p1()
{
    int chunk = blockIdx.x, h = blockIdx.y, b = blockIdx.z;
    int tid = threadIdx.x;
    int l = tid >> 3, d0 = (tid & 7) * 8;
    __shared__ float ke_s[16][16];
    __shared__ float v_s[16][64];
    float acc[8] = {0, 0, 0, 0, 0, 0, 0, 0};
    int t0 = chunk * CSZ;
    for (int tt = 0; tt < CSZ; tt += 16) {
#pragma unroll
        for (int r = 0; r < 2; r++) {
            int f = r * 128 + tid, tr = f >> 4, li = f & 15;
            ke_s[tr][li] = g_K[(b * T_ + t0 + tt + tr) * L_ + h * LH + li];
        }
#pragma unroll
        for (int r = 0; r < 2; r++) {
            int f = r * 128 + tid, tr = f >> 4, dq = f & 15;
            *(float4*)&v_s[tr][dq * 4] =
                *(const float4*)&g_V[(b * T_ + t0 + tt + tr) * D_ + h * DH + dq * 4];
        }
        __syncthreads();
#pragma unroll
        for (int k = 0; k < 16; k++) {
            float kl = ke_s[k][l];
            float4 va = *(const float4*)&v_s[k][d0];
            float4 vb = *(const float4*)&v_s[k][d0 + 4];
            acc[0] = fmaf(kl, va.x, acc[0]); acc[1] = fmaf(kl, va.y, acc[1]);
            acc[2] = fmaf(kl, va.z, acc[2]); acc[3] = fmaf(kl, va.w, acc[3]);
            acc[4] = fmaf(kl, vb.x, acc[4]); acc[5] = fmaf(kl, vb.y, acc[5]);
            acc[6] = fmaf(kl, vb.z, acc[6]); acc[7] = fmaf(kl, vb.w, acc[7]);
        }
        __syncthreads();
    }
    float* Sp = &g_S[(((b * H_ + h) * NCH + chunk) * LH + l) * DH + d0];
    *(float4*)Sp       = make_float4(acc[0], acc[1], acc[2], acc[3]);
    *(float4*)(Sp + 4) = make_float4(acc[4], acc[5], acc[6], acc[7]);
}
__global__ void state_p2()
{
    int bh = blockIdx.x, tid = threadIdx.x;
    float4 run = make_float4(0, 0, 0, 0);
    for (int c = 0; c < NCH; c++) {
        float4* p = (float4*)&g_S[(size_t)(bh * NCH + c) * (LH * DH) + tid * 4];
        float4 v = *p;
        *p = run;
        run.x += v.x; run.y += v.y; run.z += v.z; run.w += v.w;
    }
}
__global__ __launch_bounds__(64) void scan_p3()
{
    int chunk = blockIdx.x, h = blockIdx.y, b = blockIdx.z;
    int tid = threadIdx.x;
    __shared__ float ke_s[16][16];
    __shared__ float w_s[16][16];
    __shared__ float v_s[16][64];
    float carry[16];
    const float* Sp = &g_S[(size_t)((b * H_ + h) * NCH + chunk) * (LH * DH)];
#pragma unroll
    for (int l = 0; l < 16; l++) carry[l] = Sp[l * 64 + tid];
    int t0 = chunk * CSZ;

    for (int tt = 0; tt < CSZ; tt += 16) {
#pragma unroll
        for (int r = 0; r < 4; r++) {
            int f = r * 64 + tid, tr = f >> 4, li = f & 15;
            int src = (b * T_ + t0 + tt + tr) * L_ + h * LH + li;
            ke_s[tr][li] = g_K[src];
            w_s[tr][li]  = g_Q[src];
        }
#pragma unroll
        for (int r = 0; r < 4; r++) {
            int f = r * 64 + tid, tr = f >> 4, dq = f & 15;
            *(float4*)&v_s[tr][dq * 4] =
                *(const float4*)&g_V[(b * T_ + t0 + tt + tr) * D_ + h * DH + dq * 4];
        }
        __syncthreads();
#pragma unroll
        for (int k = 0; k < 16; k++) {
            float v = v_s[k][tid];
            float4 ke0 = *(const float4*)&ke_s[k][0];
            float4 ke1 = *(const float4*)&ke_s[k][4];
            float4 ke2 = *(const float4*)&ke_s[k][8];
            float4 ke3 = *(const float4*)&ke_s[k][12];
            float4 w0 = *(const float4*)&w_s[k][0];
            float4 w1 = *(const float4*)&w_s[k][4];
            float4 w2 = *(const float4*)&w_s[k][8];
            float4 w3 = *(const float4*)&w_s[k][12];
            float y = 0.f;
            carry[0]  = fmaf(ke0.x, v, carry[0]);  y = fmaf(w0.x, carry[0],  y);
            carry[1]  = fmaf(ke0.y, v, carry[1]);  y = fmaf(w0.y, carry[1],  y);
            carry[2]  = fmaf(ke0.z, v, carry[2]);  y = fmaf(w0.z, carry[2],  y);
            carry[3]  = fmaf(ke0.w, v, carry[3]);  y = fmaf(w0.w, carry[3],  y);
            carry[4]  = fmaf(ke1.x, v, carry[4]);  y = fmaf(w1.x, carry[4],  y);
            carry[5]  = fmaf(ke1.y, v, carry[5]);  y = fmaf(w1.y, carry[5],  y);
            carry[6]  = fmaf(ke1.z, v, carry[6]);  y = fmaf(w1.z, carry[6],  y);
            carry[7]  = fmaf(ke1.w, v, carry[7]);  y = fmaf(w1.w, carry[7],  y);
            carry[8]  = fmaf(ke2.x, v, carry[8]);  y = fmaf(w2.x, carry[8],  y);
            carry[9]  = fmaf(ke2.y, v, carry[9]);  y = fmaf(w2.y, carry[9],  y);
            carry[10] = fmaf(ke2.z, v, carry[10]); y = fmaf(w2.z, carry[10], y);
            carry[11] = fmaf(ke2.w, v, carry[11]); y = fmaf(w2.w, carry[11], y);
            carry[12] = fmaf(ke3.x, v, carry[12]); y = fmaf(w3.x, carry[12], y);
            carry[13] = fmaf(ke3.y, v, carry[13]); y = fmaf(w3.y, carry[13], y);
            carry[14] = fmaf(ke3.z, v, carry[14]); y = fmaf(w3.z, carry[14], y);
            carry[15] = fmaf(ke3.w, v, carry[15]); y = fmaf(w3.w, carry[15], y);
            g_yh[(b * T_ + t0 + tt + k) * D_ + h * DH + tid] =
                __half_as_ushort(__float2half(y));
        }
        __syncthreads();
    }
}

// ============================================================
// permutation (fp16 shuffle)
// ============================================================
__global__ __launch_bounds__(256) void transpose_k()
{
    int t8 = blockIdx.x, b = blockIdx.y;
    int tid = threadIdx.x;
    __shared__ unsigned short ys[8][512];
#pragma unroll
    for (int r = 0; r < 2; r++) {
        int f = r * 256 + tid, tr = f >> 6, c8 = f & 63;
        *(uint4*)&ys[tr][c8 * 8] =
            *(const uint4*)&g_yh[(size_t)(b * T_ + t8 * 8 + tr) * D_ + c8 * 8];
    }
    __syncthreads();
#pragma unroll
    for (int r = 0; r < 2; r++) {
        int p = r * 256 + tid;
        int k = p >> 6, dh = p & 63;
        unsigned short v[8];
#pragma unroll
        for (int hh = 0; hh < 8; hh++) v[hh] = ys[k][hh * 64 + dh];
        int bp = dh >> 3, e = dh & 7;
        size_t didx = (size_t)bp * (T_ * D_) + (size_t)(e * 512 + t8) * D_ + k * 64 + b * 8;
        *(uint4*)(g_Yph + didx) = *(uint4*)v;
    }
}

// ============================================================
extern "C" void kernel_launch(void* const* d_in, const int* in_sizes, int n_in,
                              void* d_out, int out_size)
{
    const float* X  = (const float*)d_in[0];
    const float* Wk = (const float*)d_in[1];
    const float* Wq = (const float*)d_in[2];
    const float* Wv = (const float*)d_in[3];
    const float* Wo = (const float*)d_in[4];
    float* out = (float*)d_out;

    unsigned short *pXh, *pYph, *pWqkvh, *pWoh;
    cudaGetSymbolAddress((void**)&pXh, g_Xh);
    cudaGetSymbolAddress((void**)&pYph, g_Yph);
    cudaGetSymbolAddress((void**)&pWqkvh, g_Wqkvh);
    cudaGetSymbolAddress((void**)&pWoh, g_Woh);

    cudaFuncSetAttribute(gemm_mma<0>, cudaFuncAttributeMaxDynamicSharedMemorySize, GEMM_SMEM);
    cudaFuncSetAttribute(gemm_mma<1>, cudaFuncAttributeMaxDynamicSharedMemorySize, GEMM_SMEM);

    // conversions
    conv_X<<<M_ * D_ / 1024, 256>>>(X);
    conv_W_all<<<dim3(16, 16, 4), 256>>>(Wq, Wk, Wv, Wo);

    // fused QKV projection (1-term fp16)
    gemm_mma<1><<<dim3(6, 256), 256, GEMM_SMEM>>>(pXh, pWqkvh, nullptr);

    // alpha cumsum + fused softmax/normalize
    alpha_p1<<<dim3(NCA, B_), 128>>>();
    alpha_p2<<<B_, 128>>>();
    alpha_p3<<<dim3(NCA, B_), 128>>>();

    // chunk-parallel state scan
    state_p1<<<dim3(NCH, H_, B_), 128>>>();
    state_p2<<<B_ * H_, 256>>>();
    scan_p3<<<dim3(NCH, H_, B_), 64>>>();

    // permutation + O projection (1-term fp16)
    transpose_k<<<dim3(T_ / 8, B_), 256>>>();
    gemm_mma<0><<<dim3(4, 256), 256, GEMM_SMEM>>>(pYph, pWoh, out);
}

// round 14
// speedup vs baseline: 1.0063x; 1.0017x over previous
#include <cuda_runtime.h>
#include <cuda_fp16.h>
#include <cstdint>

#define T_  4096
#define B_  8
#define D_  512
#define L_  128
#define H_  8
#define DH  64
#define LH  16
#define M_  (B_*T_)
#define NCH 64          // state-scan chunks
#define CSZ 64          // T_/NCH
#define NCA 128         // alpha chunks
#define CSA 32          // T_/NCA

// ---------------- scratch ----------------
__device__ float g_Q[M_*L_];
__device__ float g_K[M_*L_];
__device__ float g_V[M_*D_];
__device__ float g_csum[B_*NCA*L_];
__device__ float g_S[B_*H_*NCH*LH*DH];
__device__ unsigned short g_Xh[M_*D_];       // X fp16
__device__ unsigned short g_yh[M_*D_];       // scan out fp16 natural
__device__ unsigned short g_Yph[M_*D_];      // permuted fp16
__device__ unsigned short g_Wqkvh[(2*L_+D_)*D_];   // [768][512] fp16
__device__ unsigned short g_Woh[D_*D_];            // [512][512] fp16

// ---------------- PTX helpers ----------------
__device__ __forceinline__ uint32_t smem_u32(const void* p) {
    uint32_t a;
    asm("{ .reg .u64 t; cvta.to.shared.u64 t, %1; cvt.u32.u64 %0, t; }" : "=r"(a) : "l"(p));
    return a;
}
__device__ __forceinline__ void ldsm4(uint32_t* r, uint32_t addr) {
    asm volatile("ldmatrix.sync.aligned.m8n8.x4.shared.b16 {%0,%1,%2,%3}, [%4];"
                 : "=r"(r[0]), "=r"(r[1]), "=r"(r[2]), "=r"(r[3]) : "r"(addr));
}
__device__ __forceinline__ void mma16816(float* d, const uint32_t* a, const uint32_t* b) {
    asm volatile("mma.sync.aligned.m16n8k16.row.col.f32.f16.f16.f32 "
                 "{%0,%1,%2,%3}, {%4,%5,%6,%7}, {%8,%9}, {%0,%1,%2,%3};"
                 : "+f"(d[0]), "+f"(d[1]), "+f"(d[2]), "+f"(d[3])
                 : "r"(a[0]), "r"(a[1]), "r"(a[2]), "r"(a[3]), "r"(b[0]), "r"(b[1]));
}
#define CP_ASYNC16(dst, src) \
    asm volatile("cp.async.cg.shared.global [%0], [%1], 16;" :: "r"(dst), "l"(src))
#define CP_COMMIT() asm volatile("cp.async.commit_group;" ::: "memory")
#define CP_WAIT(n)  asm volatile("cp.async.wait_group %0;" :: "n"(n) : "memory")

// ============================================================
// fp16 1-term GEMM via mma.sync, fp32 acc. Tile 128x128, BK=32,
// 256 thr (2x4 warps, 64x32 warp tile), double-buffered cp.async.
// MODE 1: fused QKV epi (bx0 Q raw, bx1 K exp(0.125*), bx>=2 V)
// MODE 0: C[M,512] (O projection)
// ============================================================
#define ROWB 80
#define MATB (128 * ROWB)          // 10240
#define BUFB (2 * MATB)            // A,B
#define GEMM_SMEM (2 * BUFB)       // 40960

__device__ __forceinline__ void issue_loads(const unsigned short* ah,
                                            const unsigned short* bh,
                                            int k0, uint32_t smbuf, int tid)
{
#pragma unroll
    for (int half = 0; half < 2; half++) {
        int c = half * 256 + tid;
        int r = c >> 2, s = c & 3;
        uint32_t soff = (uint32_t)(r * ROWB + s * 16);
        CP_ASYNC16(smbuf + 0 * MATB + soff, ah + (size_t)r * 512 + k0 + s * 8);
        CP_ASYNC16(smbuf + 1 * MATB + soff, bh + (size_t)r * 512 + k0 + s * 8);
    }
}

template<int MODE>
__global__ __launch_bounds__(256, 2) void gemm_mma(const unsigned short* __restrict__ Ah,
                                                   const unsigned short* __restrict__ Bh,
                                                   float* __restrict__ C)
{
    extern __shared__ char sm[];
    const int tid = threadIdx.x;
    const int wid = tid >> 5, lane = tid & 31;
    const int wm = wid >> 2, wn = wid & 3;
    const int m0 = blockIdx.y * 128;
    const int n0 = blockIdx.x * 128;
    const uint32_t smb = smem_u32(sm);

    const unsigned short* ah = Ah + (size_t)m0 * 512;
    const unsigned short* bh = Bh + (size_t)n0 * 512;

    float acc[4][4][4];
#pragma unroll
    for (int i = 0; i < 4; i++)
#pragma unroll
        for (int j = 0; j < 4; j++)
#pragma unroll
            for (int e = 0; e < 4; e++) acc[i][j][e] = 0.f;

    const uint32_t a_lane = (uint32_t)((wm * 64 + (lane & 15)) * ROWB + (lane >> 4) * 16);
    const uint32_t b_lane = (uint32_t)((wn * 32 + (lane & 15)) * ROWB + (lane >> 4) * 16);

    issue_loads(ah, bh, 0, smb, tid);
    CP_COMMIT();

    const int NIT = 512 / 32;
    for (int ki = 0; ki < NIT; ki++) {
        const uint32_t buf = smb + (uint32_t)(ki & 1) * BUFB;
        if (ki + 1 < NIT) {
            issue_loads(ah, bh, (ki + 1) * 32, smb + (uint32_t)((ki + 1) & 1) * BUFB, tid);
            CP_COMMIT();
            CP_WAIT(1);
        } else {
            CP_WAIT(0);
        }
        __syncthreads();

#pragma unroll
        for (int ks = 0; ks < 2; ks++) {
            const uint32_t koff = (uint32_t)(ks * 32);
            uint32_t fBh[4][2];
#pragma unroll
            for (int p = 0; p < 2; p++) {
                uint32_t r[4];
                ldsm4(r, buf + 1 * MATB + b_lane + (uint32_t)(p * 16 * ROWB) + koff);
                fBh[2 * p][0] = r[0]; fBh[2 * p][1] = r[2];
                fBh[2 * p + 1][0] = r[1]; fBh[2 * p + 1][1] = r[3];
            }
#pragma unroll
            for (int mf = 0; mf < 4; mf++) {
                uint32_t fAh[4];
                ldsm4(fAh, buf + 0 * MATB + a_lane + (uint32_t)(mf * 16 * ROWB) + koff);
#pragma unroll
                for (int nf = 0; nf < 4; nf++)
                    mma16816(acc[mf][nf], fAh, fBh[nf]);
            }
        }
        __syncthreads();
    }

    // epilogue
    const int rr = lane >> 2, cc = (lane & 3) * 2;
    float* Cout;
    int cstride, colbase;
    bool do_exp = false;
    if (MODE == 1) {
        if (blockIdx.x == 0)      { Cout = g_Q; cstride = L_; colbase = 0; }
        else if (blockIdx.x == 1) { Cout = g_K; cstride = L_; colbase = 0; do_exp = true; }
        else                      { Cout = g_V; cstride = D_; colbase = (blockIdx.x - 2) * 128; }
    } else {
        Cout = C; cstride = D_; colbase = n0;
    }
#pragma unroll
    for (int mf = 0; mf < 4; mf++) {
#pragma unroll
        for (int nf = 0; nf < 4; nf++) {
            int row = m0 + wm * 64 + mf * 16 + rr;
            int col = colbase + wn * 32 + nf * 8 + cc;
            float d0 = acc[mf][nf][0], d1 = acc[mf][nf][1];
            float d2 = acc[mf][nf][2], d3 = acc[mf][nf][3];
            if (MODE == 1 && do_exp) {
                d0 = __expf(0.125f * d0); d1 = __expf(0.125f * d1);
                d2 = __expf(0.125f * d2); d3 = __expf(0.125f * d3);
            }
            *(float2*)(Cout + (size_t)row * cstride + col)       = make_float2(d0, d1);
            *(float2*)(Cout + (size_t)(row + 8) * cstride + col) = make_float2(d2, d3);
        }
    }
}

// ============================================================
// conversions (fp16 hi only)
// ============================================================
__global__ void conv_X(const float* __restrict__ X)
{
    int i = blockIdx.x * 256 + threadIdx.x;
    float4 v = ((const float4*)X)[i];
    ushort4 h;
    h.x = __half_as_ushort(__float2half(v.x));
    h.y = __half_as_ushort(__float2half(v.y));
    h.z = __half_as_ushort(__float2half(v.z));
    h.w = __half_as_ushort(__float2half(v.w));
    ((ushort4*)g_Xh)[i] = h;
}
// all four W[512][N] -> [N][512] fp16 transposes in one launch, tiled
__global__ __launch_bounds__(256) void conv_W_all(const float* __restrict__ Wq,
                                                  const float* __restrict__ Wk,
                                                  const float* __restrict__ Wv,
                                                  const float* __restrict__ Wo)
{
    __shared__ float ts[32][33];
    const int z = blockIdx.z;
    const float* W;
    unsigned short* Th;
    int N, roff;
    if (z == 0)      { W = Wq; Th = g_Wqkvh; N = L_; roff = 0; }
    else if (z == 1) { W = Wk; Th = g_Wqkvh; N = L_; roff = L_; }
    else if (z == 2) { W = Wv; Th = g_Wqkvh; N = D_; roff = 2 * L_; }
    else             { W = Wo; Th = g_Woh;   N = D_; roff = 0; }
    const int n0 = blockIdx.x * 32, k0 = blockIdx.y * 32;
    if (n0 >= N) return;
    const int tid = threadIdx.x;
#pragma unroll
    for (int i = 0; i < 4; i++) {
        int f = i * 256 + tid;
        int kk = f >> 5, nn = f & 31;
        ts[kk][nn] = W[(size_t)(k0 + kk) * N + n0 + nn];
    }
    __syncthreads();
#pragma unroll
    for (int i = 0; i < 4; i++) {
        int f = i * 256 + tid;
        int nn = f >> 5, kk = f & 31;
        Th[(size_t)(roff + n0 + nn) * 512 + k0 + kk] =
            __half_as_ushort(__float2half(ts[kk][nn]));
    }
}

// ============================================================
// alpha cumsum (NCA=128 chunks); p3 fuses softmax + normalize
// ============================================================
__global__ void alpha_p1()
{
    int chunk = blockIdx.x, b = blockIdx.y, l = threadIdx.x;
    float s = 0.f;
    int base = (b * T_ + chunk * CSA) * L_ + l;
    for (int i = 0; i < CSA; i++) s += g_K[base + i * L_];
    g_csum[(b * NCA + chunk) * L_ + l] = s;
}
__global__ void alpha_p2()
{
    int b = blockIdx.x, l = threadIdx.x;
    float run = 0.f;
    for (int c = 0; c < NCA; c++) {
        int idx = (b * NCA + c) * L_ + l;
        float v = g_csum[idx];
        g_csum[idx] = run;
        run += v;
    }
}
__global__ void alpha_p3()
{
    int chunk = blockIdx.x, b = blockIdx.y, l = threadIdx.x;
    float a = g_csum[(b * NCA + chunk) * L_ + l];
    int base = (b * T_ + chunk * CSA) * L_ + l;
    for (int i = 0; i < CSA; i++) {
        int idx = base + i * L_;
        a += g_K[idx];
        float q = g_Q[idx] * 0.125f;
        float m = q;
#pragma unroll
        for (int s = 8; s >= 1; s >>= 1)
            m = fmaxf(m, __shfl_xor_sync(0xffffffffu, m, s));
        float e = __expf(q - m);
        float sum = e;
#pragma unroll
        for (int s = 8; s >= 1; s >>= 1)
            sum += __shfl_xor_sync(0xffffffffu, sum, s);
        g_Q[idx] = __fdividef(e, sum * a);
    }
}

// ============================================================
// state scan (NCH=64 chunks of 64)
// ============================================================
__global__ __launch_bounds__(128) void state_p1()
{
    int chunk = blockIdx.x, h = blockIdx.y, b = blockIdx.z;
    int tid = threadIdx.x;
    int l = tid >> 3, d0 = (tid & 7) * 8;
    __shared__ float ke_s[16][16];
    __shared__ float v_s[16][64];
    float acc[8] = {0, 0, 0, 0, 0, 0, 0, 0};
    int t0 = chunk * CSZ;
    for (int tt = 0; tt < CSZ; tt += 16) {
#pragma unroll
        for (int r = 0; r < 2; r++) {
            int f = r * 128 + tid, tr = f >> 4, li = f & 15;
            ke_s[tr][li] = g_K[(b * T_ + t0 + tt + tr) * L_ + h * LH + li];
        }
#pragma unroll
        for (int r = 0; r < 2; r++) {
            int f = r * 128 + tid, tr = f >> 4, dq = f & 15;
            *(float4*)&v_s[tr][dq * 4] =
                *(const float4*)&g_V[(b * T_ + t0 + tt + tr) * D_ + h * DH + dq * 4];
        }
        __syncthreads();
#pragma unroll
        for (int k = 0; k < 16; k++) {
            float kl = ke_s[k][l];
            float4 va = *(const float4*)&v_s[k][d0];
            float4 vb = *(const float4*)&v_s[k][d0 + 4];
            acc[0] = fmaf(kl, va.x, acc[0]); acc[1] = fmaf(kl, va.y, acc[1]);
            acc[2] = fmaf(kl, va.z, acc[2]); acc[3] = fmaf(kl, va.w, acc[3]);
            acc[4] = fmaf(kl, vb.x, acc[4]); acc[5] = fmaf(kl, vb.y, acc[5]);
            acc[6] = fmaf(kl, vb.z, acc[6]); acc[7] = fmaf(kl, vb.w, acc[7]);
        }
        __syncthreads();
    }
    float* Sp = &g_S[(((b * H_ + h) * NCH + chunk) * LH + l) * DH + d0];
    *(float4*)Sp       = make_float4(acc[0], acc[1], acc[2], acc[3]);
    *(float4*)(Sp + 4) = make_float4(acc[4], acc[5], acc[6], acc[7]);
}
__global__ void state_p2()
{
    int bh = blockIdx.x, tid = threadIdx.x;
    float4 run = make_float4(0, 0, 0, 0);
    for (int c = 0; c < NCH; c++) {
        float4* p = (float4*)&g_S[(size_t)(bh * NCH + c) * (LH * DH) + tid * 4];
        float4 v = *p;
        *p = run;
        run.x += v.x; run.y += v.y; run.z += v.z; run.w += v.w;
    }
}
__global__ __launch_bounds__(64) void scan_p3()
{
    int chunk = blockIdx.x, h = blockIdx.y, b = blockIdx.z;
    int tid = threadIdx.x;
    __shared__ float ke_s[16][16];
    __shared__ float w_s[16][16];
    __shared__ float v_s[16][64];
    float carry[16];
    const float* Sp = &g_S[(size_t)((b * H_ + h) * NCH + chunk) * (LH * DH)];
#pragma unroll
    for (int l = 0; l < 16; l++) carry[l] = Sp[l * 64 + tid];
    int t0 = chunk * CSZ;

    for (int tt = 0; tt < CSZ; tt += 16) {
#pragma unroll
        for (int r = 0; r < 4; r++) {
            int f = r * 64 + tid, tr = f >> 4, li = f & 15;
            int src = (b * T_ + t0 + tt + tr) * L_ + h * LH + li;
            ke_s[tr][li] = g_K[src];
            w_s[tr][li]  = g_Q[src];
        }
#pragma unroll
        for (int r = 0; r < 4; r++) {
            int f = r * 64 + tid, tr = f >> 4, dq = f & 15;
            *(float4*)&v_s[tr][dq * 4] =
                *(const float4*)&g_V[(b * T_ + t0 + tt + tr) * D_ + h * DH + dq * 4];
        }
        __syncthreads();
#pragma unroll
        for (int k = 0; k < 16; k++) {
            float v = v_s[k][tid];
            float4 ke0 = *(const float4*)&ke_s[k][0];
            float4 ke1 = *(const float4*)&ke_s[k][4];
            float4 ke2 = *(const float4*)&ke_s[k][8];
            float4 ke3 = *(const float4*)&ke_s[k][12];
            float4 w0 = *(const float4*)&w_s[k][0];
            float4 w1 = *(const float4*)&w_s[k][4];
            float4 w2 = *(const float4*)&w_s[k][8];
            float4 w3 = *(const float4*)&w_s[k][12];
            float y = 0.f;
            carry[0]  = fmaf(ke0.x, v, carry[0]);  y = fmaf(w0.x, carry[0],  y);
            carry[1]  = fmaf(ke0.y, v, carry[1]);  y = fmaf(w0.y, carry[1],  y);
            carry[2]  = fmaf(ke0.z, v, carry[2]);  y = fmaf(w0.z, carry[2],  y);
            carry[3]  = fmaf(ke0.w, v, carry[3]);  y = fmaf(w0.w, carry[3],  y);
            carry[4]  = fmaf(ke1.x, v, carry[4]);  y = fmaf(w1.x, carry[4],  y);
            carry[5]  = fmaf(ke1.y, v, carry[5]);  y = fmaf(w1.y, carry[5],  y);
            carry[6]  = fmaf(ke1.z, v, carry[6]);  y = fmaf(w1.z, carry[6],  y);
            carry[7]  = fmaf(ke1.w, v, carry[7]);  y = fmaf(w1.w, carry[7],  y);
            carry[8]  = fmaf(ke2.x, v, carry[8]);  y = fmaf(w2.x, carry[8],  y);
            carry[9]  = fmaf(ke2.y, v, carry[9]);  y = fmaf(w2.y, carry[9],  y);
            carry[10] = fmaf(ke2.z, v, carry[10]); y = fmaf(w2.z, carry[10], y);
            carry[11] = fmaf(ke2.w, v, carry[11]); y = fmaf(w2.w, carry[11], y);
            carry[12] = fmaf(ke3.x, v, carry[12]); y = fmaf(w3.x, carry[12], y);
            carry[13] = fmaf(ke3.y, v, carry[13]); y = fmaf(w3.y, carry[13], y);
            carry[14] = fmaf(ke3.z, v, carry[14]); y = fmaf(w3.z, carry[14], y);
            carry[15] = fmaf(ke3.w, v, carry[15]); y = fmaf(w3.w, carry[15], y);
            g_yh[(b * T_ + t0 + tt + k) * D_ + h * DH + tid] =
                __half_as_ushort(__float2half(y));
        }
        __syncthreads();
    }
}

// ============================================================
// permutation (fp16 shuffle)
// ============================================================
__global__ __launch_bounds__(256) void transpose_k()
{
    int t8 = blockIdx.x, b = blockIdx.y;
    int tid = threadIdx.x;
    __shared__ unsigned short ys[8][512];
#pragma unroll
    for (int r = 0; r < 2; r++) {
        int f = r * 256 + tid, tr = f >> 6, c8 = f & 63;
        *(uint4*)&ys[tr][c8 * 8] =
            *(const uint4*)&g_yh[(size_t)(b * T_ + t8 * 8 + tr) * D_ + c8 * 8];
    }
    __syncthreads();
#pragma unroll
    for (int r = 0; r < 2; r++) {
        int p = r * 256 + tid;
        int k = p >> 6, dh = p & 63;
        unsigned short v[8];
#pragma unroll
        for (int hh = 0; hh < 8; hh++) v[hh] = ys[k][hh * 64 + dh];
        int bp = dh >> 3, e = dh & 7;
        size_t didx = (size_t)bp * (T_ * D_) + (size_t)(e * 512 + t8) * D_ + k * 64 + b * 8;
        *(uint4*)(g_Yph + didx) = *(uint4*)v;
    }
}

// ============================================================
extern "C" void kernel_launch(void* const* d_in, const int* in_sizes, int n_in,
                              void* d_out, int out_size)
{
    const float* X  = (const float*)d_in[0];
    const float* Wk = (const float*)d_in[1];
    const float* Wq = (const float*)d_in[2];
    const float* Wv = (const float*)d_in[3];
    const float* Wo = (const float*)d_in[4];
    float* out = (float*)d_out;

    unsigned short *pXh, *pYph, *pWqkvh, *pWoh;
    cudaGetSymbolAddress((void**)&pXh, g_Xh);
    cudaGetSymbolAddress((void**)&pYph, g_Yph);
    cudaGetSymbolAddress((void**)&pWqkvh, g_Wqkvh);
    cudaGetSymbolAddress((void**)&pWoh, g_Woh);

    cudaFuncSetAttribute(gemm_mma<0>, cudaFuncAttributeMaxDynamicSharedMemorySize, GEMM_SMEM);
    cudaFuncSetAttribute(gemm_mma<1>, cudaFuncAttributeMaxDynamicSharedMemorySize, GEMM_SMEM);

    // conversions
    conv_X<<<M_ * D_ / 1024, 256>>>(X);
    conv_W_all<<<dim3(16, 16, 4), 256>>>(Wq, Wk, Wv, Wo);

    // fused QKV projection (1-term fp16)
    gemm_mma<1><<<dim3(6, 256), 256, GEMM_SMEM>>>(pXh, pWqkvh, nullptr);

    // alpha cumsum + fused softmax/normalize
    alpha_p1<<<dim3(NCA, B_), 128>>>();
    alpha_p2<<<B_, 128>>>();
    alpha_p3<<<dim3(NCA, B_), 128>>>();

    // chunk-parallel state scan
    state_p1<<<dim3(NCH, H_, B_), 128>>>();
    state_p2<<<B_ * H_, 256>>>();
    scan_p3<<<dim3(NCH, H_, B_), 64>>>();

    // permutation + O projection (1-term fp16)
    transpose_k<<<dim3(T_ / 8, B_), 256>>>();
    gemm_mma<0><<<dim3(4, 256), 256, GEMM_SMEM>>>(pYph, pWoh, out);
}